// round 10
// baseline (speedup 1.0000x reference)
#include <cuda_runtime.h>
#include <stdint.h>

// ---------------- problem constants ----------------------------------------
#define NB   32
#define HH   56
#define WW   56
#define CI   256
#define CO   256
#define HP   58
#define WP   58
#define K9   9
#define NPIX (NB*HH*WW)          // 100352
#define NTILE (NPIX/128)         // 784
#define NKS   36                 // K = 2304 in steps of 64 (s4)
#define NW_ELEM (K9*CI*CO)       // 589824

#define STAGES      3
#define ROWPAD      48
#define A_BYTES_I   (128*ROWPAD)             // 6144
#define STAGE_BYTES (2*128*ROWPAD)           // 12288 (A + B)

// ---------------- device scratch --------------------------------------------
// s4 nibble-packed activations: [n][hp][wp][128B] (256 ci, 2 per byte)
__device__ int   g_act4[NB * HP * WP * 32];          // 13.8 MB
// s4 nibble-packed weights: [co][1152B] = [co][k9*32 + cw] words
__device__ int   g_wt4[CO * 288];
__device__ float g_partial[576];
__device__ float g_E;

// ---------------- PTX helpers ------------------------------------------------
__device__ __forceinline__ uint32_t smem_u32(const void* p) {
    uint32_t a;
    asm("{ .reg .u64 t; cvta.to.shared.u64 t, %1; cvt.u32.u64 %0, t; }" : "=r"(a) : "l"(p));
    return a;
}
#define CP_ASYNC16(dst, src) \
    asm volatile("cp.async.cg.shared.global [%0], [%1], 16;" \
        :: "r"(dst), "l"(__cvta_generic_to_global(src)))
#define CP_COMMIT() asm volatile("cp.async.commit_group;" ::: "memory")
#define CP_WAIT(n)  asm volatile("cp.async.wait_group %0;" :: "n"(n) : "memory")

// int4 tensor op: 16x8x64, s4 x s4 -> s32. Same fragment byte-addressing as s8 k32.
__device__ __forceinline__ void imma16864(int* d, uint32_t a0, uint32_t a1,
                                          uint32_t a2, uint32_t a3,
                                          uint32_t b0, uint32_t b1) {
    asm volatile(
        "mma.sync.aligned.m16n8k64.row.col.s32.s4.s4.s32 "
        "{%0,%1,%2,%3}, {%4,%5,%6,%7}, {%8,%9}, {%0,%1,%2,%3};"
        : "+r"(d[0]), "+r"(d[1]), "+r"(d[2]), "+r"(d[3])
        : "r"(a0), "r"(a1), "r"(a2), "r"(a3), "r"(b0), "r"(b1));
}

// ---------------- 1a/1b. E = mean|W| -----------------------------------------
__global__ void __launch_bounds__(256) reduce_absw_1(const float* __restrict__ W) {
    __shared__ float sh[256];
    int b = blockIdx.x, t = threadIdx.x;
    const float* p = W + b * 1024;
    sh[t] = fabsf(p[t]) + fabsf(p[t + 256]) + fabsf(p[t + 512]) + fabsf(p[t + 768]);
    __syncthreads();
    for (int o = 128; o > 0; o >>= 1) { if (t < o) sh[t] += sh[t + o]; __syncthreads(); }
    if (t == 0) g_partial[b] = sh[0];
}
__global__ void __launch_bounds__(256) reduce_absw_2() {
    __shared__ float sh[256];
    int t = threadIdx.x;
    float s = g_partial[t] + g_partial[t + 256];
    if (t < 64) s += g_partial[t + 512];
    sh[t] = s;
    __syncthreads();
    for (int o = 128; o > 0; o >>= 1) { if (t < o) sh[t] += sh[t + o]; __syncthreads(); }
    if (t == 0) g_E = sh[0] / (float)NW_ELEM;
}

// ---------------- 2. quantize acts -> padded s4 nibbles ----------------------
// one thread = one 32-bit word = 8 channels
__global__ void __launch_bounds__(256) quantize_x(const float* __restrict__ x) {
    int idx = blockIdx.x * 256 + threadIdx.x;          // NB*HP*WP*32
    if (idx >= NB * HP * WP * 32) return;
    int cw = idx & 31;
    int t  = idx >> 5;
    int wp = t % WP; t /= WP;
    int hp = t % HP;
    int n  = t / HP;
    uint32_t pack = 0;
    if (hp >= 1 && hp <= HH && wp >= 1 && wp <= WW) {
        const float* src = x + (((size_t)(n * HH + (hp - 1)) * WW + (wp - 1)) * CI + cw * 8);
        const float4 v0 = *reinterpret_cast<const float4*>(src);
        const float4 v1 = *reinterpret_cast<const float4*>(src + 4);
        const float f[8] = {v0.x, v0.y, v0.z, v0.w, v1.x, v1.y, v1.z, v1.w};
#pragma unroll
        for (int j = 0; j < 8; j++) {
            uint32_t a = (uint32_t)__float2int_rn(fminf(1.0f, fabsf(f[j])) * 7.0f);
            pack |= (a & 0xF) << (4 * j);
        }
    }
    g_act4[idx] = (int)pack;
}

// ---------------- 3. weight signs -> s4 nibbles [co][k9*32+cw] ----------------
__global__ void __launch_bounds__(256) wtrans(const float* __restrict__ W) {
    int idx = blockIdx.x * 256 + threadIdx.x;          // 73728 = 288*256
    if (idx >= CO * 288) return;
    int co = idx & 255;
    int t  = idx >> 8;             // 0..287 = k9*32 + cw
    int k9 = t >> 5;
    int cw = t & 31;
    uint32_t pack = 0;
#pragma unroll
    for (int j = 0; j < 4; j++) {
        // two channels per iteration to keep loads simple: do 8 singles instead
    }
#pragma unroll
    for (int j = 0; j < 8; j++) {
        float f = W[((size_t)(k9 * CI + cw * 8 + j)) * CO + co];
        int s = (f > 0.0f) - (f < 0.0f);       // -1,0,1
        pack |= ((uint32_t)s & 0xF) << (4 * j); // -1 -> 0xF (s4 two's complement)
    }
    g_wt4[co * 288 + t] = (int)pack;
}

// ---------------- 4. IMMA s4 implicit GEMM (all batches) ---------------------
// grid (784, 2); block 256 = 8 warps (4M x 2N), warp tile 32x64, K-step 64.
__global__ void __launch_bounds__(256, 2) conv_imma(const float* __restrict__ bias,
                                                    float* __restrict__ out) {
    __shared__ char sbuf[STAGES * STAGE_BYTES];        // 36864 B
    __shared__ float sbias[128];

    const int tid = threadIdx.x;
    const int pbase = blockIdx.x * 128;
    const int nbase = blockIdx.y * 128;

    if (tid < 128) sbias[tid] = bias[nbase + tid];

    // producer: thread -> one A 16B chunk + one B 16B chunk per k-step
    const int pr = tid >> 1, half = tid & 1;
    const int P = pbase + pr;
    const int pn = P / 3136;
    const int prm = P - pn * 3136;
    const int ph = prm / 56;
    const int pw = prm - ph * 56;
    const char* aBase = (const char*)g_act4
        + ((size_t)((pn * HP + ph) * WP + pw)) * 128 + half * 16;   // 128B per pixel
    const char* bBase = (const char*)g_wt4 + (size_t)(nbase + pr) * 1152 + half * 16;
    const uint32_t dstOff = pr * ROWPAD + half * 16;
    const uint32_t sb = smem_u32(sbuf);

    const int lane = tid & 31, wid = tid >> 5;
    const int mgrp = wid & 3;          // M offset = mgrp*32
    const int ngrp = wid >> 2;         // N offset = ngrp*64
    const uint32_t aoff = (uint32_t)((mgrp * 32 + (lane >> 2)) * ROWPAD + (lane & 3) * 4);
    const uint32_t boff = (uint32_t)((ngrp * 64 + (lane >> 2)) * ROWPAD + (lane & 3) * 4) + A_BYTES_I;

    int acc[2][8][4];
#pragma unroll
    for (int ma = 0; ma < 2; ma++)
#pragma unroll
        for (int na = 0; na < 8; na++)
#pragma unroll
            for (int j = 0; j < 4; j++) acc[ma][na][j] = 0;

    // k-step ks (0..35): k9 = ks>>2 (tap), cc = ks&3 (64-ci chunk = 32B)
#pragma unroll
    for (int ks = 0; ks < STAGES - 1; ks++) {
        const int k9 = ks >> 2, cc = ks & 3;
        const int kh = k9 / 3, kw = k9 - kh * 3;
        const uint32_t slot = sb + ks * STAGE_BYTES;
        CP_ASYNC16(slot + dstOff, aBase + (kh * WP + kw) * 128 + cc * 32);
        CP_ASYNC16(slot + A_BYTES_I + dstOff, bBase + k9 * 128 + cc * 32);
        CP_COMMIT();
    }

    int slotIdx = 0;
    int loadSlot = STAGES - 1;
    for (int ks = 0; ks < NKS; ks++) {
        CP_WAIT(STAGES - 2);
        __syncthreads();

        {
            const int kn = ks + STAGES - 1;
            if (kn < NKS) {
                const int k9 = kn >> 2, cc = kn & 3;
                const int kh = k9 / 3, kw = k9 - kh * 3;
                const uint32_t slot = sb + loadSlot * STAGE_BYTES;
                CP_ASYNC16(slot + dstOff, aBase + (kh * WP + kw) * 128 + cc * 32);
                CP_ASYNC16(slot + A_BYTES_I + dstOff, bBase + k9 * 128 + cc * 32);
            }
            CP_COMMIT();
        }

        const char* s = sbuf + slotIdx * STAGE_BYTES;
        uint32_t af[2][4];
#pragma unroll
        for (int ma = 0; ma < 2; ma++) {
            const char* ab = s + aoff + ma * (16 * ROWPAD);
            af[ma][0] = *(const uint32_t*)(ab);
            af[ma][1] = *(const uint32_t*)(ab + 8 * ROWPAD);
            af[ma][2] = *(const uint32_t*)(ab + 16);
            af[ma][3] = *(const uint32_t*)(ab + 8 * ROWPAD + 16);
        }
        uint32_t bf[8][2];
#pragma unroll
        for (int na = 0; na < 8; na++) {
            const char* bb = s + boff + na * (8 * ROWPAD);
            bf[na][0] = *(const uint32_t*)(bb);
            bf[na][1] = *(const uint32_t*)(bb + 16);
        }
#pragma unroll
        for (int na = 0; na < 8; na++)
#pragma unroll
            for (int ma = 0; ma < 2; ma++)
                imma16864(acc[ma][na], af[ma][0], af[ma][1], af[ma][2], af[ma][3],
                          bf[na][0], bf[na][1]);

        slotIdx++;  if (slotIdx == STAGES) slotIdx = 0;
        loadSlot++; if (loadSlot == STAGES) loadSlot = 0;
    }

    const float scale = g_E * (1.0f / 7.0f);
    const int orow0 = pbase + mgrp * 32 + (lane >> 2);
    const int ocol0 = nbase + ngrp * 64 + (lane & 3) * 2;
#pragma unroll
    for (int ma = 0; ma < 2; ma++) {
#pragma unroll
        for (int na = 0; na < 8; na++) {
            const int row = orow0 + ma * 16;
            const int col = ocol0 + na * 8;
            const float b0 = sbias[col - nbase];
            const float b1 = sbias[col - nbase + 1];
            float2 v0, v1;
            v0.x = (float)acc[ma][na][0] * scale + b0;
            v0.y = (float)acc[ma][na][1] * scale + b1;
            v1.x = (float)acc[ma][na][2] * scale + b0;
            v1.y = (float)acc[ma][na][3] * scale + b1;
            *reinterpret_cast<float2*>(out + (size_t)row * CO + col) = v0;
            *reinterpret_cast<float2*>(out + (size_t)(row + 8) * CO + col) = v1;
        }
    }
}

// ---------------- launch -----------------------------------------------------
extern "C" void kernel_launch(void* const* d_in, const int* in_sizes, int n_in,
                              void* d_out, int out_size) {
    const float* x = (const float*)d_in[0];
    const float* W = (const float*)d_in[1];
    const float* b = (const float*)d_in[2];
    float* out = (float*)d_out;

    int qtot = NB * HP * WP * 32;
    quantize_x<<<(qtot + 255) / 256, 256>>>(x);
    reduce_absw_1<<<576, 256>>>(W);
    reduce_absw_2<<<1, 256>>>();
    wtrans<<<(CO * 288 + 255) / 256, 256>>>(W);

    conv_imma<<<dim3(NTILE, 2), 256>>>(b, out);
}

// round 11
// speedup vs baseline: 4.5364x; 4.5364x over previous
#include <cuda_runtime.h>
#include <stdint.h>

// ---------------- problem constants ----------------------------------------
#define NB   32
#define HH   56
#define WW   56
#define CI   256
#define CO   256
#define HP   58
#define WP   58
#define NW_ELEM (9*CI*CO)        // 589824
#define NTPI 784                 // 28x28 tiles per image
#define NT   (NB*NTPI)           // 25088 Winograd tiles
#define MT   196                 // 25088/128 M-tiles
#define NKS  8                   // K = 256 in 32-byte steps

#define STAGES      3
#define ROWPAD      48
#define A_BYTES_I   (128*ROWPAD)             // 6144
#define STAGE_BYTES (2*128*ROWPAD)           // 12288

// ---------------- device scratch --------------------------------------------
__device__ int   g_act[NB * HP * WP * 64];       // padded s8 acts, 27.5 MB
__device__ int   g_V[16 * NT * 64];              // transformed acts s8, 103 MB
__device__ char  g_U[16 * CO * CI];              // transformed weights s8, 1 MB
__device__ int   g_C[(size_t)16 * NT * CO];      // GEMM out s32, 411 MB
__device__ float g_partial[576];
__device__ float g_E;

// ---------------- PTX helpers ------------------------------------------------
__device__ __forceinline__ uint32_t smem_u32(const void* p) {
    uint32_t a;
    asm("{ .reg .u64 t; cvta.to.shared.u64 t, %1; cvt.u32.u64 %0, t; }" : "=r"(a) : "l"(p));
    return a;
}
#define CP_ASYNC16(dst, src) \
    asm volatile("cp.async.cg.shared.global [%0], [%1], 16;" \
        :: "r"(dst), "l"(__cvta_generic_to_global(src)))
#define CP_COMMIT() asm volatile("cp.async.commit_group;" ::: "memory")
#define CP_WAIT(n)  asm volatile("cp.async.wait_group %0;" :: "n"(n) : "memory")

__device__ __forceinline__ void imma16832(int* d, uint32_t a0, uint32_t a1,
                                          uint32_t a2, uint32_t a3,
                                          uint32_t b0, uint32_t b1) {
    asm volatile(
        "mma.sync.aligned.m16n8k32.row.col.s32.s8.s8.s32 "
        "{%0,%1,%2,%3}, {%4,%5,%6,%7}, {%8,%9}, {%0,%1,%2,%3};"
        : "+r"(d[0]), "+r"(d[1]), "+r"(d[2]), "+r"(d[3])
        : "r"(a0), "r"(a1), "r"(a2), "r"(a3), "r"(b0), "r"(b1));
}

// ---------------- 1a/1b. E = mean|W| -----------------------------------------
__global__ void __launch_bounds__(256) reduce_absw_1(const float* __restrict__ W) {
    __shared__ float sh[256];
    int b = blockIdx.x, t = threadIdx.x;
    const float* p = W + b * 1024;
    sh[t] = fabsf(p[t]) + fabsf(p[t + 256]) + fabsf(p[t + 512]) + fabsf(p[t + 768]);
    __syncthreads();
    for (int o = 128; o > 0; o >>= 1) { if (t < o) sh[t] += sh[t + o]; __syncthreads(); }
    if (t == 0) g_partial[b] = sh[0];
}
__global__ void __launch_bounds__(256) reduce_absw_2() {
    __shared__ float sh[256];
    int t = threadIdx.x;
    float s = g_partial[t] + g_partial[t + 256];
    if (t < 64) s += g_partial[t + 512];
    sh[t] = s;
    __syncthreads();
    for (int o = 128; o > 0; o >>= 1) { if (t < o) sh[t] += sh[t + o]; __syncthreads(); }
    if (t == 0) g_E = sh[0] / (float)NW_ELEM;
}

// ---------------- 2. quantize acts -> padded s8 packs ------------------------
__global__ void __launch_bounds__(256) quantize_x(const float* __restrict__ x) {
    int idx = blockIdx.x * 256 + threadIdx.x;          // NB*HP*WP*64
    if (idx >= NB * HP * WP * 64) return;
    int c4 = idx & 63;
    int t  = idx >> 6;
    int wp = t % WP; t /= WP;
    int hp = t % HP;
    int n  = t / HP;
    int pack = 0;
    if (hp >= 1 && hp <= HH && wp >= 1 && wp <= WW) {
        const float4 v = *reinterpret_cast<const float4*>(
            x + (((size_t)(n * HH + (hp - 1)) * WW + (wp - 1)) * CI + c4 * 4));
        int a0 = __float2int_rn(fminf(1.0f, fabsf(v.x)) * 7.0f);
        int a1 = __float2int_rn(fminf(1.0f, fabsf(v.y)) * 7.0f);
        int a2 = __float2int_rn(fminf(1.0f, fabsf(v.z)) * 7.0f);
        int a3 = __float2int_rn(fminf(1.0f, fabsf(v.w)) * 7.0f);
        pack = (a0 & 0xff) | ((a1 & 0xff) << 8) | ((a2 & 0xff) << 16) | ((a3 & 0xff) << 24);
    }
    g_act[idx] = pack;
}

// ---------------- 3. weight transform: U2 = (2G) w (2G)^T --------------------
// thread = (co, ci); writes g_U[pos][co][ci] s8 (|U2| <= 9)
__global__ void __launch_bounds__(256) wg_transform(const float* __restrict__ W) {
    int idx = blockIdx.x * 256 + threadIdx.x;          // 65536
    if (idx >= CO * CI) return;
    int ci = idx & 255;
    int co = idx >> 8;
    int w[3][3];
#pragma unroll
    for (int kh = 0; kh < 3; kh++)
#pragma unroll
        for (int kw = 0; kw < 3; kw++) {
            float f = W[((size_t)((kh * 3 + kw) * CI + ci)) * CO + co];
            w[kh][kw] = (f > 0.0f) - (f < 0.0f);
        }
    int t[4][3];
#pragma unroll
    for (int c = 0; c < 3; c++) {
        t[0][c] = 2 * w[0][c];
        t[1][c] = w[0][c] + w[1][c] + w[2][c];
        t[2][c] = w[0][c] - w[1][c] + w[2][c];
        t[3][c] = 2 * w[2][c];
    }
#pragma unroll
    for (int i = 0; i < 4; i++) {
        int u0 = 2 * t[i][0];
        int u1 = t[i][0] + t[i][1] + t[i][2];
        int u2 = t[i][0] - t[i][1] + t[i][2];
        int u3 = 2 * t[i][2];
        g_U[(((i * 4 + 0) * CO + co) << 8) + ci] = (char)u0;
        g_U[(((i * 4 + 1) * CO + co) << 8) + ci] = (char)u1;
        g_U[(((i * 4 + 2) * CO + co) << 8) + ci] = (char)u2;
        g_U[(((i * 4 + 3) * CO + co) << 8) + ci] = (char)u3;
    }
}

// ---------------- 4. input transform: V = B^T d B (byte-SIMD) ----------------
// thread = (tile T, ci-word cw); d in [0,7], V in [-28,28] per byte
__global__ void __launch_bounds__(256) in_transform() {
    int idx = blockIdx.x * 256 + threadIdx.x;          // NT*64 = 1605632
    if (idx >= NT * 64) return;
    int cw = idx & 63;
    int T  = idx >> 6;
    int n  = T / NTPI;
    int rem = T - n * NTPI;
    int ti = rem / 28;
    int tj = rem - ti * 28;

    unsigned d[16];
#pragma unroll
    for (int r = 0; r < 4; r++)
#pragma unroll
        for (int c = 0; c < 4; c++)
            d[r * 4 + c] = (unsigned)g_act[((n * HP + 2 * ti + r) * WP + (2 * tj + c)) * 64 + cw];

    unsigned t0[4], t1[4], t2[4], t3[4];
#pragma unroll
    for (int c = 0; c < 4; c++) {
        t0[c] = __vsub4(d[0 * 4 + c], d[2 * 4 + c]);
        t1[c] = __vadd4(d[1 * 4 + c], d[2 * 4 + c]);
        t2[c] = __vsub4(d[2 * 4 + c], d[1 * 4 + c]);
        t3[c] = __vsub4(d[1 * 4 + c], d[3 * 4 + c]);
    }
    unsigned V[16];
#pragma unroll
    for (int i = 0; i < 4; i++) {
        const unsigned* t = (i == 0) ? t0 : (i == 1) ? t1 : (i == 2) ? t2 : t3;
        V[i * 4 + 0] = __vsub4(t[0], t[2]);
        V[i * 4 + 1] = __vadd4(t[1], t[2]);
        V[i * 4 + 2] = __vsub4(t[2], t[1]);
        V[i * 4 + 3] = __vsub4(t[1], t[3]);
    }
#pragma unroll
    for (int p = 0; p < 16; p++)
        g_V[(p * NT + T) * 64 + cw] = (int)V[p];
}

// ---------------- 5. 16 batched s8 IMMA GEMMs --------------------------------
// grid (196, 2, 16); block 256 = 8 warps (4M x 2N), warp tile 32x64, K=256
__global__ void __launch_bounds__(256, 2) wino_gemm() {
    __shared__ char sbuf[STAGES * STAGE_BYTES];        // 36864 B

    const int tid = threadIdx.x;
    const int pbase = blockIdx.x * 128;
    const int nbase = blockIdx.y * 128;
    const int pos = blockIdx.z;

    const int pr = tid >> 1, half = tid & 1;
    const char* aBase = (const char*)g_V + ((size_t)(pos * NT + pbase + pr)) * 256 + half * 16;
    const char* bBase = (const char*)g_U + ((size_t)(pos * CO + nbase + pr)) * 256 + half * 16;
    const uint32_t dstOff = pr * ROWPAD + half * 16;
    const uint32_t sb = smem_u32(sbuf);

    const int lane = tid & 31, wid = tid >> 5;
    const int mgrp = wid & 3;
    const int ngrp = wid >> 2;
    const uint32_t aoff = (uint32_t)((mgrp * 32 + (lane >> 2)) * ROWPAD + (lane & 3) * 4);
    const uint32_t boff = (uint32_t)((ngrp * 64 + (lane >> 2)) * ROWPAD + (lane & 3) * 4) + A_BYTES_I;

    int acc[2][8][4];
#pragma unroll
    for (int ma = 0; ma < 2; ma++)
#pragma unroll
        for (int na = 0; na < 8; na++)
#pragma unroll
            for (int j = 0; j < 4; j++) acc[ma][na][j] = 0;

#pragma unroll
    for (int ks = 0; ks < STAGES - 1; ks++) {
        const uint32_t slot = sb + ks * STAGE_BYTES;
        CP_ASYNC16(slot + dstOff, aBase + ks * 32);
        CP_ASYNC16(slot + A_BYTES_I + dstOff, bBase + ks * 32);
        CP_COMMIT();
    }

    int slotIdx = 0;
    int loadSlot = STAGES - 1;
    for (int ks = 0; ks < NKS; ks++) {
        CP_WAIT(STAGES - 2);
        __syncthreads();

        {
            const int kn = ks + STAGES - 1;
            if (kn < NKS) {
                const uint32_t slot = sb + loadSlot * STAGE_BYTES;
                CP_ASYNC16(slot + dstOff, aBase + kn * 32);
                CP_ASYNC16(slot + A_BYTES_I + dstOff, bBase + kn * 32);
            }
            CP_COMMIT();
        }

        const char* s = sbuf + slotIdx * STAGE_BYTES;
        uint32_t af[2][4];
#pragma unroll
        for (int ma = 0; ma < 2; ma++) {
            const char* ab = s + aoff + ma * (16 * ROWPAD);
            af[ma][0] = *(const uint32_t*)(ab);
            af[ma][1] = *(const uint32_t*)(ab + 8 * ROWPAD);
            af[ma][2] = *(const uint32_t*)(ab + 16);
            af[ma][3] = *(const uint32_t*)(ab + 8 * ROWPAD + 16);
        }
        uint32_t bf[8][2];
#pragma unroll
        for (int na = 0; na < 8; na++) {
            const char* bb = s + boff + na * (8 * ROWPAD);
            bf[na][0] = *(const uint32_t*)(bb);
            bf[na][1] = *(const uint32_t*)(bb + 16);
        }
#pragma unroll
        for (int na = 0; na < 8; na++)
#pragma unroll
            for (int ma = 0; ma < 2; ma++)
                imma16832(acc[ma][na], af[ma][0], af[ma][1], af[ma][2], af[ma][3],
                          bf[na][0], bf[na][1]);

        slotIdx++;  if (slotIdx == STAGES) slotIdx = 0;
        loadSlot++; if (loadSlot == STAGES) loadSlot = 0;
    }

    // store raw s32 C
    const int row0 = pbase + mgrp * 32 + (lane >> 2);
    const int col0 = nbase + ngrp * 64 + (lane & 3) * 2;
    int* Cb = g_C + (size_t)pos * NT * CO;
#pragma unroll
    for (int ma = 0; ma < 2; ma++) {
#pragma unroll
        for (int na = 0; na < 8; na++) {
            const int row = row0 + ma * 16;
            const int col = col0 + na * 8;
            *reinterpret_cast<int2*>(Cb + (size_t)row * CO + col) =
                make_int2(acc[ma][na][0], acc[ma][na][1]);
            *reinterpret_cast<int2*>(Cb + (size_t)(row + 8) * CO + col) =
                make_int2(acc[ma][na][2], acc[ma][na][3]);
        }
    }
}

// ---------------- 6. output transform: Y = A^T M A, scale, bias --------------
// 8 warps/block; warp = one tile, lane = co within 32-block, 8 co-blocks
__global__ void __launch_bounds__(256) out_transform(const float* __restrict__ bias,
                                                     float* __restrict__ out) {
    const int lane = threadIdx.x & 31, wid = threadIdx.x >> 5;
    const int T = blockIdx.x * 8 + wid;
    const int n  = T / NTPI;
    const int rem = T - n * NTPI;
    const int ti = rem / 28;
    const int tj = rem - ti * 28;
    const float scale = g_E * (1.0f / 28.0f);

#pragma unroll 1
    for (int cb = 0; cb < 8; cb++) {
        const int co = cb * 32 + lane;
        int m[16];
#pragma unroll
        for (int p = 0; p < 16; p++)
            m[p] = g_C[((size_t)p * NT + T) * CO + co];

        int P0[4], P1[4];
#pragma unroll
        for (int c = 0; c < 4; c++) {
            P0[c] = m[0 * 4 + c] + m[1 * 4 + c] + m[2 * 4 + c];
            P1[c] = m[1 * 4 + c] - m[2 * 4 + c] - m[3 * 4 + c];
        }
        const int y00 = P0[0] + P0[1] + P0[2];
        const int y01 = P0[1] - P0[2] - P0[3];
        const int y10 = P1[0] + P1[1] + P1[2];
        const int y11 = P1[1] - P1[2] - P1[3];

        const float bv = bias[co];
        const int h = 2 * ti, w = 2 * tj;
        float* o00 = out + (((size_t)(n * HH + h) * WW + w) * CO + co);
        o00[0]              = (float)y00 * scale + bv;
        o00[CO]             = (float)y01 * scale + bv;
        o00[(size_t)WW*CO]      = (float)y10 * scale + bv;
        o00[(size_t)WW*CO + CO] = (float)y11 * scale + bv;
    }
}

// ---------------- launch -----------------------------------------------------
extern "C" void kernel_launch(void* const* d_in, const int* in_sizes, int n_in,
                              void* d_out, int out_size) {
    const float* x = (const float*)d_in[0];
    const float* W = (const float*)d_in[1];
    const float* b = (const float*)d_in[2];
    float* out = (float*)d_out;

    int qtot = NB * HP * WP * 64;
    quantize_x<<<(qtot + 255) / 256, 256>>>(x);
    reduce_absw_1<<<576, 256>>>(W);
    reduce_absw_2<<<1, 256>>>();
    wg_transform<<<CO * CI / 256, 256>>>(W);
    in_transform<<<(NT * 64 + 255) / 256, 256>>>();
    wino_gemm<<<dim3(MT, 2, 16), 256>>>();
    out_transform<<<NT / 8, 256>>>(b, out);
}

// round 12
// speedup vs baseline: 5.6793x; 1.2519x over previous
#include <cuda_runtime.h>
#include <cuda_bf16.h>
#include <stdint.h>

// ---------------- problem constants ----------------------------------------
#define NB   32
#define HH   56
#define WW   56
#define CI   256
#define CO   256
#define HP   58
#define WP   58
#define NW_ELEM (9*CI*CO)        // 589824
#define NTPI 784                 // 28x28 tiles per image
#define NT   (NB*NTPI)           // 25088 Winograd tiles
#define MT   196                 // 25088/128 M-tiles
#define NKS  16                  // K = 256 in 16-element bf16 steps (32 B)

#define STAGES      3
#define ROWPAD      48
#define A_BYTES_I   (128*ROWPAD)             // 6144
#define STAGE_BYTES (2*128*ROWPAD)           // 12288

// ---------------- device scratch --------------------------------------------
__device__ int            g_act[NB * HP * WP * 64];        // padded s8 acts, 27.5 MB
__device__ __nv_bfloat16  g_V[(size_t)16 * NT * CI];       // transformed acts, 205 MB
__device__ __nv_bfloat16  g_U[16 * CO * CI];               // transformed weights, 2 MB
__device__ float          g_C[(size_t)16 * NT * CO];       // GEMM out fp32, 411 MB
__device__ float g_partial[576];
__device__ float g_E;

// ---------------- PTX helpers ------------------------------------------------
__device__ __forceinline__ uint32_t smem_u32(const void* p) {
    uint32_t a;
    asm("{ .reg .u64 t; cvta.to.shared.u64 t, %1; cvt.u32.u64 %0, t; }" : "=r"(a) : "l"(p));
    return a;
}
#define CP_ASYNC16(dst, src) \
    asm volatile("cp.async.cg.shared.global [%0], [%1], 16;" \
        :: "r"(dst), "l"(__cvta_generic_to_global(src)))
#define CP_COMMIT() asm volatile("cp.async.commit_group;" ::: "memory")
#define CP_WAIT(n)  asm volatile("cp.async.wait_group %0;" :: "n"(n) : "memory")

__device__ __forceinline__ void hmma16816(float* d, uint32_t a0, uint32_t a1,
                                          uint32_t a2, uint32_t a3,
                                          uint32_t b0, uint32_t b1) {
    asm volatile(
        "mma.sync.aligned.m16n8k16.row.col.f32.bf16.bf16.f32 "
        "{%0,%1,%2,%3}, {%4,%5,%6,%7}, {%8,%9}, {%0,%1,%2,%3};"
        : "+f"(d[0]), "+f"(d[1]), "+f"(d[2]), "+f"(d[3])
        : "r"(a0), "r"(a1), "r"(a2), "r"(a3), "r"(b0), "r"(b1));
}

// ---------------- 1a/1b. E = mean|W| -----------------------------------------
__global__ void __launch_bounds__(256) reduce_absw_1(const float* __restrict__ W) {
    __shared__ float sh[256];
    int b = blockIdx.x, t = threadIdx.x;
    const float* p = W + b * 1024;
    sh[t] = fabsf(p[t]) + fabsf(p[t + 256]) + fabsf(p[t + 512]) + fabsf(p[t + 768]);
    __syncthreads();
    for (int o = 128; o > 0; o >>= 1) { if (t < o) sh[t] += sh[t + o]; __syncthreads(); }
    if (t == 0) g_partial[b] = sh[0];
}
__global__ void __launch_bounds__(256) reduce_absw_2() {
    __shared__ float sh[256];
    int t = threadIdx.x;
    float s = g_partial[t] + g_partial[t + 256];
    if (t < 64) s += g_partial[t + 512];
    sh[t] = s;
    __syncthreads();
    for (int o = 128; o > 0; o >>= 1) { if (t < o) sh[t] += sh[t + o]; __syncthreads(); }
    if (t == 0) g_E = sh[0] / (float)NW_ELEM;
}

// ---------------- 2. quantize acts -> padded s8 packs ------------------------
__global__ void __launch_bounds__(256) quantize_x(const float* __restrict__ x) {
    int idx = blockIdx.x * 256 + threadIdx.x;          // NB*HP*WP*64
    if (idx >= NB * HP * WP * 64) return;
    int c4 = idx & 63;
    int t  = idx >> 6;
    int wp = t % WP; t /= WP;
    int hp = t % HP;
    int n  = t / HP;
    int pack = 0;
    if (hp >= 1 && hp <= HH && wp >= 1 && wp <= WW) {
        const float4 v = *reinterpret_cast<const float4*>(
            x + (((size_t)(n * HH + (hp - 1)) * WW + (wp - 1)) * CI + c4 * 4));
        int a0 = __float2int_rn(fminf(1.0f, fabsf(v.x)) * 7.0f);
        int a1 = __float2int_rn(fminf(1.0f, fabsf(v.y)) * 7.0f);
        int a2 = __float2int_rn(fminf(1.0f, fabsf(v.z)) * 7.0f);
        int a3 = __float2int_rn(fminf(1.0f, fabsf(v.w)) * 7.0f);
        pack = (a0 & 0xff) | ((a1 & 0xff) << 8) | ((a2 & 0xff) << 16) | ((a3 & 0xff) << 24);
    }
    g_act[idx] = pack;
}

// ---------------- 3. weight transform: U2 = (2G) w (2G)^T -> bf16 ------------
__global__ void __launch_bounds__(256) wg_transform(const float* __restrict__ W) {
    int idx = blockIdx.x * 256 + threadIdx.x;          // 65536
    if (idx >= CO * CI) return;
    int ci = idx & 255;
    int co = idx >> 8;
    int w[3][3];
#pragma unroll
    for (int kh = 0; kh < 3; kh++)
#pragma unroll
        for (int kw = 0; kw < 3; kw++) {
            float f = W[((size_t)((kh * 3 + kw) * CI + ci)) * CO + co];
            w[kh][kw] = (f > 0.0f) - (f < 0.0f);
        }
    int t[4][3];
#pragma unroll
    for (int c = 0; c < 3; c++) {
        t[0][c] = 2 * w[0][c];
        t[1][c] = w[0][c] + w[1][c] + w[2][c];
        t[2][c] = w[0][c] - w[1][c] + w[2][c];
        t[3][c] = 2 * w[2][c];
    }
#pragma unroll
    for (int i = 0; i < 4; i++) {
        int u[4];
        u[0] = 2 * t[i][0];
        u[1] = t[i][0] + t[i][1] + t[i][2];
        u[2] = t[i][0] - t[i][1] + t[i][2];
        u[3] = 2 * t[i][2];
#pragma unroll
        for (int j = 0; j < 4; j++)
            g_U[(((i * 4 + j) * CO + co) << 8) + ci] = __float2bfloat16((float)u[j]);
    }
}

// ---------------- 4. input transform: V = B^T d B -> bf16 --------------------
// thread = (tile T, ci-word cw of 4 channels); d in [0,7], V in [-28,28]
__global__ void __launch_bounds__(256) in_transform() {
    int idx = blockIdx.x * 256 + threadIdx.x;          // NT*64
    if (idx >= NT * 64) return;
    int cw = idx & 63;
    int T  = idx >> 6;
    int n  = T / NTPI;
    int rem = T - n * NTPI;
    int ti = rem / 28;
    int tj = rem - ti * 28;

    unsigned d[16];
#pragma unroll
    for (int r = 0; r < 4; r++)
#pragma unroll
        for (int c = 0; c < 4; c++)
            d[r * 4 + c] = (unsigned)g_act[((n * HP + 2 * ti + r) * WP + (2 * tj + c)) * 64 + cw];

    unsigned t0[4], t1[4], t2[4], t3[4];
#pragma unroll
    for (int c = 0; c < 4; c++) {
        t0[c] = __vsub4(d[0 * 4 + c], d[2 * 4 + c]);
        t1[c] = __vadd4(d[1 * 4 + c], d[2 * 4 + c]);
        t2[c] = __vsub4(d[2 * 4 + c], d[1 * 4 + c]);
        t3[c] = __vsub4(d[1 * 4 + c], d[3 * 4 + c]);
    }
    unsigned V[16];
#pragma unroll
    for (int i = 0; i < 4; i++) {
        const unsigned* t = (i == 0) ? t0 : (i == 1) ? t1 : (i == 2) ? t2 : t3;
        V[i * 4 + 0] = __vsub4(t[0], t[2]);
        V[i * 4 + 1] = __vadd4(t[1], t[2]);
        V[i * 4 + 2] = __vsub4(t[2], t[1]);
        V[i * 4 + 3] = __vsub4(t[1], t[3]);
    }
#pragma unroll
    for (int p = 0; p < 16; p++) {
        const unsigned v = V[p];
        union { __nv_bfloat16 h[4]; uint2 u; } o;
        o.h[0] = __float2bfloat16((float)(((int)(v << 24)) >> 24));
        o.h[1] = __float2bfloat16((float)(((int)(v << 16)) >> 24));
        o.h[2] = __float2bfloat16((float)(((int)(v <<  8)) >> 24));
        o.h[3] = __float2bfloat16((float)(((int)v) >> 24));
        *reinterpret_cast<uint2*>(&g_V[((size_t)p * NT + T) * CI + cw * 4]) = o.u;
    }
}

// ---------------- 5. 16 batched bf16 HMMA GEMMs ------------------------------
// grid (196, 2, 16); block 256 = 8 warps (4M x 2N), warp tile 32x64, K-step 16
__global__ void __launch_bounds__(256, 2) wino_gemm() {
    __shared__ char sbuf[STAGES * STAGE_BYTES];        // 36864 B

    const int tid = threadIdx.x;
    const int pbase = blockIdx.x * 128;
    const int nbase = blockIdx.y * 128;
    const int pos = blockIdx.z;

    const int pr = tid >> 1, half = tid & 1;
    const char* aBase = (const char*)g_V + ((size_t)pos * NT + pbase + pr) * 512 + half * 16;
    const char* bBase = (const char*)g_U + ((size_t)pos * CO + nbase + pr) * 512 + half * 16;
    const uint32_t dstOff = pr * ROWPAD + half * 16;
    const uint32_t sb = smem_u32(sbuf);

    const int lane = tid & 31, wid = tid >> 5;
    const int mgrp = wid & 3;
    const int ngrp = wid >> 2;
    const uint32_t aoff = (uint32_t)((mgrp * 32 + (lane >> 2)) * ROWPAD + (lane & 3) * 4);
    const uint32_t boff = (uint32_t)((ngrp * 64 + (lane >> 2)) * ROWPAD + (lane & 3) * 4) + A_BYTES_I;

    float acc[2][8][4];
#pragma unroll
    for (int ma = 0; ma < 2; ma++)
#pragma unroll
        for (int na = 0; na < 8; na++)
#pragma unroll
            for (int j = 0; j < 4; j++) acc[ma][na][j] = 0.0f;

#pragma unroll
    for (int ks = 0; ks < STAGES - 1; ks++) {
        const uint32_t slot = sb + ks * STAGE_BYTES;
        CP_ASYNC16(slot + dstOff, aBase + ks * 32);
        CP_ASYNC16(slot + A_BYTES_I + dstOff, bBase + ks * 32);
        CP_COMMIT();
    }

    int slotIdx = 0;
    int loadSlot = STAGES - 1;
    for (int ks = 0; ks < NKS; ks++) {
        CP_WAIT(STAGES - 2);
        __syncthreads();

        {
            const int kn = ks + STAGES - 1;
            if (kn < NKS) {
                const uint32_t slot = sb + loadSlot * STAGE_BYTES;
                CP_ASYNC16(slot + dstOff, aBase + kn * 32);
                CP_ASYNC16(slot + A_BYTES_I + dstOff, bBase + kn * 32);
            }
            CP_COMMIT();
        }

        const char* s = sbuf + slotIdx * STAGE_BYTES;
        uint32_t af[2][4];
#pragma unroll
        for (int ma = 0; ma < 2; ma++) {
            const char* ab = s + aoff + ma * (16 * ROWPAD);
            af[ma][0] = *(const uint32_t*)(ab);
            af[ma][1] = *(const uint32_t*)(ab + 8 * ROWPAD);
            af[ma][2] = *(const uint32_t*)(ab + 16);
            af[ma][3] = *(const uint32_t*)(ab + 8 * ROWPAD + 16);
        }
        uint32_t bf[8][2];
#pragma unroll
        for (int na = 0; na < 8; na++) {
            const char* bb = s + boff + na * (8 * ROWPAD);
            bf[na][0] = *(const uint32_t*)(bb);
            bf[na][1] = *(const uint32_t*)(bb + 16);
        }
#pragma unroll
        for (int na = 0; na < 8; na++)
#pragma unroll
            for (int ma = 0; ma < 2; ma++)
                hmma16816(acc[ma][na], af[ma][0], af[ma][1], af[ma][2], af[ma][3],
                          bf[na][0], bf[na][1]);

        slotIdx++;  if (slotIdx == STAGES) slotIdx = 0;
        loadSlot++; if (loadSlot == STAGES) loadSlot = 0;
    }

    // store fp32 C (exact integers)
    const int row0 = pbase + mgrp * 32 + (lane >> 2);
    const int col0 = nbase + ngrp * 64 + (lane & 3) * 2;
    float* Cb = g_C + (size_t)pos * NT * CO;
#pragma unroll
    for (int ma = 0; ma < 2; ma++) {
#pragma unroll
        for (int na = 0; na < 8; na++) {
            const int row = row0 + ma * 16;
            const int col = col0 + na * 8;
            *reinterpret_cast<float2*>(Cb + (size_t)row * CO + col) =
                make_float2(acc[ma][na][0], acc[ma][na][1]);
            *reinterpret_cast<float2*>(Cb + (size_t)(row + 8) * CO + col) =
                make_float2(acc[ma][na][2], acc[ma][na][3]);
        }
    }
}

// ---------------- 6. output transform: Y = A^T M A, scale, bias --------------
__global__ void __launch_bounds__(256) out_transform(const float* __restrict__ bias,
                                                     float* __restrict__ out) {
    const int lane = threadIdx.x & 31, wid = threadIdx.x >> 5;
    const int T = blockIdx.x * 8 + wid;
    const int n  = T / NTPI;
    const int rem = T - n * NTPI;
    const int ti = rem / 28;
    const int tj = rem - ti * 28;
    const float scale = g_E * (1.0f / 28.0f);

#pragma unroll 1
    for (int cb = 0; cb < 8; cb++) {
        const int co = cb * 32 + lane;
        float m[16];
#pragma unroll
        for (int p = 0; p < 16; p++)
            m[p] = g_C[((size_t)p * NT + T) * CO + co];

        float P0[4], P1[4];
#pragma unroll
        for (int c = 0; c < 4; c++) {
            P0[c] = m[0 * 4 + c] + m[1 * 4 + c] + m[2 * 4 + c];
            P1[c] = m[1 * 4 + c] - m[2 * 4 + c] - m[3 * 4 + c];
        }
        const float y00 = P0[0] + P0[1] + P0[2];
        const float y01 = P0[1] - P0[2] - P0[3];
        const float y10 = P1[0] + P1[1] + P1[2];
        const float y11 = P1[1] - P1[2] - P1[3];

        const float bv = bias[co];
        const int h = 2 * ti, w = 2 * tj;
        float* o00 = out + (((size_t)(n * HH + h) * WW + w) * CO + co);
        o00[0]                  = y00 * scale + bv;
        o00[CO]                 = y01 * scale + bv;
        o00[(size_t)WW*CO]      = y10 * scale + bv;
        o00[(size_t)WW*CO + CO] = y11 * scale + bv;
    }
}

// ---------------- launch -----------------------------------------------------
extern "C" void kernel_launch(void* const* d_in, const int* in_sizes, int n_in,
                              void* d_out, int out_size) {
    const float* x = (const float*)d_in[0];
    const float* W = (const float*)d_in[1];
    const float* b = (const float*)d_in[2];
    float* out = (float*)d_out;

    int qtot = NB * HP * WP * 64;
    quantize_x<<<(qtot + 255) / 256, 256>>>(x);
    reduce_absw_1<<<576, 256>>>(W);
    reduce_absw_2<<<1, 256>>>();
    wg_transform<<<CO * CI / 256, 256>>>(W);
    in_transform<<<(NT * 64 + 255) / 256, 256>>>();
    wino_gemm<<<dim3(MT, 2, 16), 256>>>();
    out_transform<<<NT / 8, 256>>>(b, out);
}